// round 7
// baseline (speedup 1.0000x reference)
#include <cuda_runtime.h>
#include <cuda_bf16.h>
#include <cstdint>

#define NNODES 100000
#define DEG     16
#define DIM     128
#define NEG_SLOPE 0.01f
#define LDA 136   // bf16 elems per smem row (128 + 8 pad) -> conflict-free ldmatrix

// ---------------- scratch (static device globals; no allocation) ----------------
__device__ float g_z [NNODES * DIM];
__device__ float g_zi[NNODES * DIM];
__device__ float g_h [NNODES * DIM];
__device__ float g_ss[NNODES];
__device__ float g_sd[NNODES];

// ---------------- PTX helpers ----------------
static __device__ __forceinline__ uint32_t sptr(const void* p) {
    return (uint32_t)__cvta_generic_to_shared(p);
}
static __device__ __forceinline__ void ldsm4(uint32_t* r, uint32_t addr) {
    asm volatile("ldmatrix.sync.aligned.m8n8.x4.shared.b16 {%0,%1,%2,%3}, [%4];"
                 : "=r"(r[0]), "=r"(r[1]), "=r"(r[2]), "=r"(r[3]) : "r"(addr));
}
static __device__ __forceinline__ void ldsm4t(uint32_t* r, uint32_t addr) {
    asm volatile("ldmatrix.sync.aligned.m8n8.x4.trans.shared.b16 {%0,%1,%2,%3}, [%4];"
                 : "=r"(r[0]), "=r"(r[1]), "=r"(r[2]), "=r"(r[3]) : "r"(addr));
}
static __device__ __forceinline__ void mma16816(float* c, const uint32_t* a,
                                                uint32_t b0, uint32_t b1) {
    asm volatile(
        "mma.sync.aligned.m16n8k16.row.col.f32.bf16.bf16.f32 "
        "{%0,%1,%2,%3}, {%4,%5,%6,%7}, {%8,%9}, {%0,%1,%2,%3};"
        : "+f"(c[0]), "+f"(c[1]), "+f"(c[2]), "+f"(c[3])
        : "r"(a[0]), "r"(a[1]), "r"(a[2]), "r"(a[3]), "r"(b0), "r"(b1));
}
static __device__ __forceinline__ void split_bf16(float v, __nv_bfloat16& hi, __nv_bfloat16& lo) {
    hi = __float2bfloat16(v);
    lo = __float2bfloat16(v - __bfloat162float(hi));
}

// fill sB[k][n] (hi/lo) from row-major W[n][k]; 512 threads
static __device__ __forceinline__ void fill_w(const float* __restrict__ W,
                                              __nv_bfloat16* sBhi, __nv_bfloat16* sBlo,
                                              int tid) {
#pragma unroll
    for (int p = 0; p < 8; p++) {
        int idx = tid + p * 512;          // 0..4095 (float4 units)
        int k4  = idx >> 7;               // 0..31
        int n   = idx & 127;
        float4 v = *(const float4*)&W[n * DIM + k4 * 4];
        float vv[4] = {v.x, v.y, v.z, v.w};
#pragma unroll
        for (int i = 0; i < 4; i++) {
            __nv_bfloat16 hi, lo;
            split_bf16(vv[i], hi, lo);
            int k = k4 * 4 + i;
            sBhi[k * LDA + n] = hi;
            sBlo[k * LDA + n] = lo;
        }
    }
}

// ---------------------------------------------------------------------------
// GEMM: per 128-row tile, in ONE pass:
//   z  = h@Ww^T (+ fused s_src/s_dst),  zi = h@Wu^T
// 512 threads, 16 warps; warp tile 16x64; both B matrices resident in smem.
// ---------------------------------------------------------------------------
__global__ __launch_bounds__(512) void gat_gemm_kernel(
    const float* __restrict__ h,
    const float* __restrict__ Ww,
    const float* __restrict__ Wu,
    const float* __restrict__ Wa,
    float* __restrict__ z,
    float* __restrict__ zi,
    float* __restrict__ ssrc,
    float* __restrict__ sdst)
{
    extern __shared__ __align__(16) char smem_raw[];
    __nv_bfloat16* sAhi  = (__nv_bfloat16*)smem_raw;
    __nv_bfloat16* sAlo  = sAhi  + 128 * LDA;
    __nv_bfloat16* sBhi0 = sAlo  + 128 * LDA;
    __nv_bfloat16* sBlo0 = sBhi0 + 128 * LDA;
    __nv_bfloat16* sBhi1 = sBlo0 + 128 * LDA;
    __nv_bfloat16* sBlo1 = sBhi1 + 128 * LDA;
    float*         sred  = (float*)(sBlo1 + 128 * LDA);  // [256]: 0..127 src, 128..255 dst

    const int tid  = threadIdx.x;
    const int lane = tid & 31;
    const int warp = tid >> 5;      // 0..15
    const int wm   = warp & 7;      // 16-row strip
    const int wn   = warp >> 3;     // 64-col strip
    const int row0 = blockIdx.x * 128;

    if (tid < 256) sred[tid] = 0.f;

    // ---- stage A tile (fp32 -> bf16 hi/lo) ----
#pragma unroll
    for (int p = 0; p < 8; p++) {
        int idx = tid + p * 512;    // 0..4095 (float4 units)
        int r   = idx >> 5;
        int c4  = idx & 31;
        float4 v = make_float4(0.f, 0.f, 0.f, 0.f);
        int row = row0 + r;
        if (row < NNODES) v = *(const float4*)&h[row * DIM + c4 * 4];
        float vv[4] = {v.x, v.y, v.z, v.w};
        __nv_bfloat16 hi[4], lo[4];
#pragma unroll
        for (int i = 0; i < 4; i++) split_bf16(vv[i], hi[i], lo[i]);
        __nv_bfloat162* ph = (__nv_bfloat162*)&sAhi[r * LDA + c4 * 4];
        __nv_bfloat162* pl = (__nv_bfloat162*)&sAlo[r * LDA + c4 * 4];
        ph[0] = __halves2bfloat162(hi[0], hi[1]);
        ph[1] = __halves2bfloat162(hi[2], hi[3]);
        pl[0] = __halves2bfloat162(lo[0], lo[1]);
        pl[1] = __halves2bfloat162(lo[2], lo[3]);
    }
    fill_w(Ww, sBhi0, sBlo0, tid);
    fill_w(Wu, sBhi1, sBlo1, tid);
    __syncthreads();

    // ---- single fused mainloop: both accumulator sets share A fragments ----
    float cz[8][4], cu[8][4];
#pragma unroll
    for (int t = 0; t < 8; t++)
#pragma unroll
        for (int i = 0; i < 4; i++) { cz[t][i] = 0.f; cu[t][i] = 0.f; }

    const int arow  = lane & 15;
    const int acolh = (lane >> 4) * 8;

#pragma unroll 1
    for (int kb = 0; kb < DIM; kb += 16) {
        uint32_t ahi[4], alo[4];
        {
            int off = (wm * 16 + arow) * LDA + kb + acolh;
            ldsm4(ahi, sptr(&sAhi[off]));
            ldsm4(alo, sptr(&sAlo[off]));
        }
#pragma unroll
        for (int q = 0; q < 4; q++) {
            int boff = (kb + arow) * LDA + wn * 64 + q * 16 + acolh;
            uint32_t bh0[4], bl0[4], bh1[4], bl1[4];
            ldsm4t(bh0, sptr(&sBhi0[boff]));
            ldsm4t(bl0, sptr(&sBlo0[boff]));
            ldsm4t(bh1, sptr(&sBhi1[boff]));
            ldsm4t(bl1, sptr(&sBlo1[boff]));
#pragma unroll
            for (int half = 0; half < 2; half++) {
                int t = q * 2 + half, hh = half * 2;
                mma16816(cz[t], ahi, bh0[hh], bh0[hh + 1]);
                mma16816(cu[t], ahi, bh1[hh], bh1[hh + 1]);
                mma16816(cz[t], ahi, bl0[hh], bl0[hh + 1]);
                mma16816(cu[t], ahi, bl1[hh], bl1[hh + 1]);
                mma16816(cz[t], alo, bh0[hh], bh0[hh + 1]);
                mma16816(cu[t], alo, bh1[hh], bh1[hh + 1]);
            }
        }
    }

    // ---- epilogue: write z, zi, fused s_src/s_dst ----
    float ps[2] = {0.f, 0.f}, pd[2] = {0.f, 0.f};
#pragma unroll
    for (int t = 0; t < 8; t++) {
        int col = wn * 64 + t * 8 + (lane & 3) * 2;
        float as0 = Wa[col],       as1 = Wa[col + 1];
        float ad0 = Wa[DIM + col], ad1 = Wa[DIM + col + 1];
#pragma unroll
        for (int hh = 0; hh < 2; hh++) {
            int row = row0 + wm * 16 + hh * 8 + (lane >> 2);
            if (row < NNODES) {
                *(float2*)&z [row * DIM + col] = make_float2(cz[t][hh * 2], cz[t][hh * 2 + 1]);
                *(float2*)&zi[row * DIM + col] = make_float2(cu[t][hh * 2], cu[t][hh * 2 + 1]);
            }
            ps[hh] = fmaf(cz[t][hh * 2], as0, fmaf(cz[t][hh * 2 + 1], as1, ps[hh]));
            pd[hh] = fmaf(cz[t][hh * 2], ad0, fmaf(cz[t][hh * 2 + 1], ad1, pd[hh]));
        }
    }
    // reduce across the 4 lanes of each quad (they hold different columns)
#pragma unroll
    for (int hh = 0; hh < 2; hh++) {
#pragma unroll
        for (int off = 1; off <= 2; off <<= 1) {
            ps[hh] += __shfl_xor_sync(0xffffffffu, ps[hh], off);
            pd[hh] += __shfl_xor_sync(0xffffffffu, pd[hh], off);
        }
    }
    if ((lane & 3) == 0) {
#pragma unroll
        for (int hh = 0; hh < 2; hh++) {
            int lr = wm * 16 + hh * 8 + (lane >> 2);
            atomicAdd(&sred[lr],       ps[hh]);
            atomicAdd(&sred[128 + lr], pd[hh]);
        }
    }
    __syncthreads();
    if (tid < 256) {
        int which = tid >> 7;           // 0 = src, 1 = dst
        int r     = tid & 127;
        int row   = row0 + r;
        if (row < NNODES) {
            float s = sred[which * 128 + r];
            if (which) sdst[row] = s; else ssrc[row] = s;
        }
    }
}

// ---------------------------------------------------------------------------
// Attention kernel: one warp per destination node (unchanged, known-good)
// ---------------------------------------------------------------------------
__global__ __launch_bounds__(256) void gat_attn_kernel(
    const int*   __restrict__ edge_src,
    const float* __restrict__ edge_d,
    const float* __restrict__ Wv,
    const float* __restrict__ Wa,
    const float* __restrict__ z,
    const float* __restrict__ zi,
    const float* __restrict__ ssrc,
    const float* __restrict__ sdst,
    float* __restrict__ out)
{
    const int warp = (blockIdx.x * blockDim.x + threadIdx.x) >> 5;
    const int lane = threadIdx.x & 31;
    if (warp >= NNODES) return;

    const float cE = Wv[0] * Wa[2 * DIM];
    const float sd = sdst[warp];

    int   src = 0;
    float e   = -1e30f;
    if (lane < DEG) {
        src = edge_src[warp * DEG + lane];
        float ev = ssrc[src] + sd + cE * edge_d[warp * DEG + lane];
        e = (ev > 0.f) ? ev : NEG_SLOPE * ev;
    }

    float m = e;
#pragma unroll
    for (int off = 8; off >= 1; off >>= 1)
        m = fmaxf(m, __shfl_xor_sync(0xffffffffu, m, off));

    float ex = (lane < DEG) ? expf(e - m) : 0.f;
    float s  = ex;
#pragma unroll
    for (int off = 8; off >= 1; off >>= 1)
        s += __shfl_xor_sync(0xffffffffu, s, off);

    const float alpha = ex / s;

    const int col = lane * 4;
    float4 acc = make_float4(0.f, 0.f, 0.f, 0.f);
#pragma unroll
    for (int j = 0; j < DEG; j++) {
        int   sj = __shfl_sync(0xffffffffu, src,   j);
        float aj = __shfl_sync(0xffffffffu, alpha, j);
        float4 v = *(const float4*)&z[sj * DIM + col];
        acc.x = fmaf(aj, v.x, acc.x);
        acc.y = fmaf(aj, v.y, acc.y);
        acc.z = fmaf(aj, v.z, acc.z);
        acc.w = fmaf(aj, v.w, acc.w);
    }

    float4 zv = *(const float4*)&zi[warp * DIM + col];
    float4 o;
    o.x = fmaxf(zv.x + acc.x, 0.f);
    o.y = fmaxf(zv.y + acc.y, 0.f);
    o.z = fmaxf(zv.z + acc.z, 0.f);
    o.w = fmaxf(zv.w + acc.w, 0.f);
    *(float4*)&out[warp * DIM + col] = o;
}

// ---------------------------------------------------------------------------
extern "C" void kernel_launch(void* const* d_in, const int* in_sizes, int n_in,
                              void* d_out, int out_size) {
    const float* attr     = (const float*)d_in[0];
    const float* edge_d   = (const float*)d_in[1];
    const float* W_V1     = (const float*)d_in[2];
    const float* W_W1     = (const float*)d_in[3];
    const float* W_U1     = (const float*)d_in[4];
    const float* W_a1     = (const float*)d_in[5];
    const float* W_V2     = (const float*)d_in[6];
    const float* W_W2     = (const float*)d_in[7];
    const float* W_U2     = (const float*)d_in[8];
    const float* W_a2     = (const float*)d_in[9];
    const int*   edge_src = (const int*)  d_in[10];
    float* out = (float*)d_out;

    static float *zp = nullptr, *zip = nullptr, *hp = nullptr, *ssp = nullptr, *sdp = nullptr;
    static int smem_bytes = 0;
    if (!zp) {
        cudaGetSymbolAddress((void**)&zp,  g_z);
        cudaGetSymbolAddress((void**)&zip, g_zi);
        cudaGetSymbolAddress((void**)&hp,  g_h);
        cudaGetSymbolAddress((void**)&ssp, g_ss);
        cudaGetSymbolAddress((void**)&sdp, g_sd);
        smem_bytes = 6 * 128 * LDA * (int)sizeof(__nv_bfloat16) + 256 * (int)sizeof(float);
        cudaFuncSetAttribute(gat_gemm_kernel,
                             cudaFuncAttributeMaxDynamicSharedMemorySize, smem_bytes);
    }

    const int gemm_blocks = (NNODES + 127) / 128;     // 782
    const int attn_blocks = (NNODES + 7) / 8;         // 12500

    // Layer 1
    gat_gemm_kernel<<<gemm_blocks, 512, smem_bytes>>>(attr, W_W1, W_U1, W_a1, zp, zip, ssp, sdp);
    gat_attn_kernel<<<attn_blocks, 256>>>(edge_src, edge_d, W_V1, W_a1,
                                          zp, zip, ssp, sdp, hp);
    // Layer 2
    gat_gemm_kernel<<<gemm_blocks, 512, smem_bytes>>>(hp, W_W2, W_U2, W_a2, zp, zip, ssp, sdp);
    gat_attn_kernel<<<attn_blocks, 256>>>(edge_src, edge_d, W_V2, W_a2,
                                          zp, zip, ssp, sdp, out);
}

// round 14
// speedup vs baseline: 1.4288x; 1.4288x over previous
#include <cuda_runtime.h>
#include <cuda_fp16.h>
#include <cuda_bf16.h>
#include <cstdint>

#define NNODES 100000
#define DEG     16
#define DIM     128
#define NTILES  ((NNODES + 127) / 128)     // 782
#define NEG_SLOPE 0.01f
#define LDA 136   // bf16 elems per smem row (128 + 8 pad) -> conflict-free ldmatrix

// ---------------- scratch (static device globals; no allocation) ----------------
__device__ __half g_z [NNODES * DIM];
__device__ __half g_zi[NNODES * DIM];
__device__ __half g_h [NNODES * DIM];
__device__ float  g_ss[NNODES];
__device__ float  g_sd[NNODES];

// ---------------- PTX helpers ----------------
static __device__ __forceinline__ uint32_t sptr(const void* p) {
    return (uint32_t)__cvta_generic_to_shared(p);
}
static __device__ __forceinline__ void ldsm4(uint32_t* r, uint32_t addr) {
    asm volatile("ldmatrix.sync.aligned.m8n8.x4.shared.b16 {%0,%1,%2,%3}, [%4];"
                 : "=r"(r[0]), "=r"(r[1]), "=r"(r[2]), "=r"(r[3]) : "r"(addr));
}
static __device__ __forceinline__ void ldsm4t(uint32_t* r, uint32_t addr) {
    asm volatile("ldmatrix.sync.aligned.m8n8.x4.trans.shared.b16 {%0,%1,%2,%3}, [%4];"
                 : "=r"(r[0]), "=r"(r[1]), "=r"(r[2]), "=r"(r[3]) : "r"(addr));
}
static __device__ __forceinline__ void mma16816(float* c, const uint32_t* a,
                                                uint32_t b0, uint32_t b1) {
    asm volatile(
        "mma.sync.aligned.m16n8k16.row.col.f32.bf16.bf16.f32 "
        "{%0,%1,%2,%3}, {%4,%5,%6,%7}, {%8,%9}, {%0,%1,%2,%3};"
        : "+f"(c[0]), "+f"(c[1]), "+f"(c[2]), "+f"(c[3])
        : "r"(a[0]), "r"(a[1]), "r"(a[2]), "r"(a[3]), "r"(b0), "r"(b1));
}
static __device__ __forceinline__ void split_bf16(float v, __nv_bfloat16& hi, __nv_bfloat16& lo) {
    hi = __float2bfloat16(v);
    lo = __float2bfloat16(v - __bfloat162float(hi));
}

// fill sB[k][n] (hi/lo) from row-major W[n][k]; 512 threads
static __device__ __forceinline__ void fill_w(const float* __restrict__ W,
                                              __nv_bfloat16* sBhi, __nv_bfloat16* sBlo,
                                              int tid) {
#pragma unroll
    for (int p = 0; p < 8; p++) {
        int idx = tid + p * 512;          // 0..4095 (float4 units)
        int k4  = idx >> 7;               // 0..31
        int n   = idx & 127;
        float4 v = *(const float4*)&W[n * DIM + k4 * 4];
        float vv[4] = {v.x, v.y, v.z, v.w};
#pragma unroll
        for (int i = 0; i < 4; i++) {
            __nv_bfloat16 hi, lo;
            split_bf16(vv[i], hi, lo);
            int k = k4 * 4 + i;
            sBhi[k * LDA + n] = hi;
            sBlo[k * LDA + n] = lo;
        }
    }
}

// load 4 consecutive input values as float4 (fp32 or fp16 source)
template <typename Tin>
static __device__ __forceinline__ float4 load4(const Tin* p) {
    if constexpr (sizeof(Tin) == 4) {
        return *(const float4*)p;
    } else {
        float2 raw = *(const float2*)p;                  // 4 halves
        __half2 h01 = *(__half2*)&raw.x;
        __half2 h23 = *(__half2*)&raw.y;
        float2 f01 = __half22float2(h01);
        float2 f23 = __half22float2(h23);
        return make_float4(f01.x, f01.y, f23.x, f23.y);
    }
}

// ---------------------------------------------------------------------------
// Persistent GEMM: weights staged ONCE per CTA; grid-stride over 128-row tiles.
//   z  = h@Ww^T (+ fused s_src/s_dst),  zi = h@Wu^T    (bf16x3, fp32 accum)
// 512 threads, 16 warps; warp tile 16x64; outputs stored fp16.
// ---------------------------------------------------------------------------
template <typename Tin>
__global__ __launch_bounds__(512) void gat_gemm_kernel(
    const Tin*   __restrict__ h,
    const float* __restrict__ Ww,
    const float* __restrict__ Wu,
    const float* __restrict__ Wa,
    __half* __restrict__ z,
    __half* __restrict__ zi,
    float*  __restrict__ ssrc,
    float*  __restrict__ sdst)
{
    extern __shared__ __align__(16) char smem_raw[];
    __nv_bfloat16* sAhi  = (__nv_bfloat16*)smem_raw;
    __nv_bfloat16* sAlo  = sAhi  + 128 * LDA;
    __nv_bfloat16* sBhi0 = sAlo  + 128 * LDA;
    __nv_bfloat16* sBlo0 = sBhi0 + 128 * LDA;
    __nv_bfloat16* sBhi1 = sBlo0 + 128 * LDA;
    __nv_bfloat16* sBlo1 = sBhi1 + 128 * LDA;
    float*         sred  = (float*)(sBlo1 + 128 * LDA);  // [256]: 0..127 src, 128..255 dst

    const int tid  = threadIdx.x;
    const int lane = tid & 31;
    const int warp = tid >> 5;      // 0..15
    const int wm   = warp & 7;      // 16-row strip
    const int wn   = warp >> 3;     // 64-col strip

    // ---- stage both weight matrices ONCE ----
    fill_w(Ww, sBhi0, sBlo0, tid);
    fill_w(Wu, sBhi1, sBlo1, tid);

    const int arow  = lane & 15;
    const int acolh = (lane >> 4) * 8;

    for (int tile = blockIdx.x; tile < NTILES; tile += gridDim.x) {
        const int row0 = tile * 128;
        if (tid < 256) sred[tid] = 0.f;

        // ---- stage A tile (input -> bf16 hi/lo) ----
#pragma unroll
        for (int p = 0; p < 8; p++) {
            int idx = tid + p * 512;    // 0..4095 (4-elem units)
            int r   = idx >> 5;
            int c4  = idx & 31;
            float4 v = make_float4(0.f, 0.f, 0.f, 0.f);
            int row = row0 + r;
            if (row < NNODES) v = load4(&h[row * DIM + c4 * 4]);
            float vv[4] = {v.x, v.y, v.z, v.w};
            __nv_bfloat16 hi[4], lo[4];
#pragma unroll
            for (int i = 0; i < 4; i++) split_bf16(vv[i], hi[i], lo[i]);
            __nv_bfloat162* ph = (__nv_bfloat162*)&sAhi[r * LDA + c4 * 4];
            __nv_bfloat162* pl = (__nv_bfloat162*)&sAlo[r * LDA + c4 * 4];
            ph[0] = __halves2bfloat162(hi[0], hi[1]);
            ph[1] = __halves2bfloat162(hi[2], hi[3]);
            pl[0] = __halves2bfloat162(lo[0], lo[1]);
            pl[1] = __halves2bfloat162(lo[2], lo[3]);
        }
        __syncthreads();   // A ready, sred zeroed, (first iter: B ready)

        // ---- fused mainloop: both accumulator sets share A fragments ----
        float cz[8][4], cu[8][4];
#pragma unroll
        for (int t = 0; t < 8; t++)
#pragma unroll
            for (int i = 0; i < 4; i++) { cz[t][i] = 0.f; cu[t][i] = 0.f; }

#pragma unroll 1
        for (int kb = 0; kb < DIM; kb += 16) {
            uint32_t ahi[4], alo[4];
            {
                int off = (wm * 16 + arow) * LDA + kb + acolh;
                ldsm4(ahi, sptr(&sAhi[off]));
                ldsm4(alo, sptr(&sAlo[off]));
            }
#pragma unroll
            for (int q = 0; q < 4; q++) {
                int boff = (kb + arow) * LDA + wn * 64 + q * 16 + acolh;
                uint32_t bh0[4], bl0[4], bh1[4], bl1[4];
                ldsm4t(bh0, sptr(&sBhi0[boff]));
                ldsm4t(bl0, sptr(&sBlo0[boff]));
                ldsm4t(bh1, sptr(&sBhi1[boff]));
                ldsm4t(bl1, sptr(&sBlo1[boff]));
#pragma unroll
                for (int half = 0; half < 2; half++) {
                    int t = q * 2 + half, hh = half * 2;
                    mma16816(cz[t], ahi, bh0[hh], bh0[hh + 1]);
                    mma16816(cu[t], ahi, bh1[hh], bh1[hh + 1]);
                    mma16816(cz[t], ahi, bl0[hh], bl0[hh + 1]);
                    mma16816(cu[t], ahi, bl1[hh], bl1[hh + 1]);
                    mma16816(cz[t], alo, bh0[hh], bh0[hh + 1]);
                    mma16816(cu[t], alo, bh1[hh], bh1[hh + 1]);
                }
            }
        }

        // ---- epilogue: write z, zi (fp16), fused s_src/s_dst ----
        float ps[2] = {0.f, 0.f}, pd[2] = {0.f, 0.f};
#pragma unroll
        for (int t = 0; t < 8; t++) {
            int col = wn * 64 + t * 8 + (lane & 3) * 2;
            float as0 = Wa[col],       as1 = Wa[col + 1];
            float ad0 = Wa[DIM + col], ad1 = Wa[DIM + col + 1];
#pragma unroll
            for (int hh = 0; hh < 2; hh++) {
                int row = row0 + wm * 16 + hh * 8 + (lane >> 2);
                if (row < NNODES) {
                    *(__half2*)&z [row * DIM + col] =
                        __floats2half2_rn(cz[t][hh * 2], cz[t][hh * 2 + 1]);
                    *(__half2*)&zi[row * DIM + col] =
                        __floats2half2_rn(cu[t][hh * 2], cu[t][hh * 2 + 1]);
                }
                ps[hh] = fmaf(cz[t][hh * 2], as0, fmaf(cz[t][hh * 2 + 1], as1, ps[hh]));
                pd[hh] = fmaf(cz[t][hh * 2], ad0, fmaf(cz[t][hh * 2 + 1], ad1, pd[hh]));
            }
        }
        // reduce across the 4 lanes of each quad (different columns)
#pragma unroll
        for (int hh = 0; hh < 2; hh++) {
#pragma unroll
            for (int off = 1; off <= 2; off <<= 1) {
                ps[hh] += __shfl_xor_sync(0xffffffffu, ps[hh], off);
                pd[hh] += __shfl_xor_sync(0xffffffffu, pd[hh], off);
            }
        }
        if ((lane & 3) == 0) {
#pragma unroll
            for (int hh = 0; hh < 2; hh++) {
                int lr = wm * 16 + hh * 8 + (lane >> 2);
                atomicAdd(&sred[lr],       ps[hh]);
                atomicAdd(&sred[128 + lr], pd[hh]);
            }
        }
        __syncthreads();
        if (tid < 256) {
            int which = tid >> 7;           // 0 = src, 1 = dst
            int r     = tid & 127;
            int row   = row0 + r;
            if (row < NNODES) {
                float s = sred[which * 128 + r];
                if (which) sdst[row] = s; else ssrc[row] = s;
            }
        }
        __syncthreads();   // protect sA / sred before next tile
    }
}

// ---------------------------------------------------------------------------
// Attention kernel: one warp per destination node; z/zi in fp16.
// ---------------------------------------------------------------------------
template <bool OUT_HALF>
__global__ __launch_bounds__(256) void gat_attn_kernel(
    const int*    __restrict__ edge_src,
    const float*  __restrict__ edge_d,
    const float*  __restrict__ Wv,
    const float*  __restrict__ Wa,
    const __half* __restrict__ z,
    const __half* __restrict__ zi,
    const float*  __restrict__ ssrc,
    const float*  __restrict__ sdst,
    void* __restrict__ outv)
{
    const int warp = (blockIdx.x * blockDim.x + threadIdx.x) >> 5;
    const int lane = threadIdx.x & 31;
    if (warp >= NNODES) return;

    const float cE = Wv[0] * Wa[2 * DIM];
    const float sd = sdst[warp];

    int   src = 0;
    float e   = -1e30f;
    if (lane < DEG) {
        src = edge_src[warp * DEG + lane];
        float ev = ssrc[src] + sd + cE * edge_d[warp * DEG + lane];
        e = (ev > 0.f) ? ev : NEG_SLOPE * ev;
    }

    float m = e;
#pragma unroll
    for (int off = 8; off >= 1; off >>= 1)
        m = fmaxf(m, __shfl_xor_sync(0xffffffffu, m, off));

    float ex = (lane < DEG) ? expf(e - m) : 0.f;
    float s  = ex;
#pragma unroll
    for (int off = 8; off >= 1; off >>= 1)
        s += __shfl_xor_sync(0xffffffffu, s, off);

    const float alpha = ex / s;

    const int col = lane * 4;
    float4 acc = make_float4(0.f, 0.f, 0.f, 0.f);
#pragma unroll
    for (int j = 0; j < DEG; j++) {
        int   sj = __shfl_sync(0xffffffffu, src,   j);
        float aj = __shfl_sync(0xffffffffu, alpha, j);
        float2 raw = *(const float2*)&z[sj * DIM + col];   // 4 halves
        float2 f01 = __half22float2(*(__half2*)&raw.x);
        float2 f23 = __half22float2(*(__half2*)&raw.y);
        acc.x = fmaf(aj, f01.x, acc.x);
        acc.y = fmaf(aj, f01.y, acc.y);
        acc.z = fmaf(aj, f23.x, acc.z);
        acc.w = fmaf(aj, f23.y, acc.w);
    }

    float2 rawzi = *(const float2*)&zi[warp * DIM + col];
    float2 zi01 = __half22float2(*(__half2*)&rawzi.x);
    float2 zi23 = __half22float2(*(__half2*)&rawzi.y);

    float4 o;
    o.x = fmaxf(zi01.x + acc.x, 0.f);
    o.y = fmaxf(zi01.y + acc.y, 0.f);
    o.z = fmaxf(zi23.x + acc.z, 0.f);
    o.w = fmaxf(zi23.y + acc.w, 0.f);

    if constexpr (OUT_HALF) {
        __half* out = (__half*)outv;
        float2 packed;
        *(__half2*)&packed.x = __floats2half2_rn(o.x, o.y);
        *(__half2*)&packed.y = __floats2half2_rn(o.z, o.w);
        *(float2*)&out[warp * DIM + col] = packed;
    } else {
        float* out = (float*)outv;
        *(float4*)&out[warp * DIM + col] = o;
    }
}

// ---------------------------------------------------------------------------
extern "C" void kernel_launch(void* const* d_in, const int* in_sizes, int n_in,
                              void* d_out, int out_size) {
    const float* attr     = (const float*)d_in[0];
    const float* edge_d   = (const float*)d_in[1];
    const float* W_V1     = (const float*)d_in[2];
    const float* W_W1     = (const float*)d_in[3];
    const float* W_U1     = (const float*)d_in[4];
    const float* W_a1     = (const float*)d_in[5];
    const float* W_V2     = (const float*)d_in[6];
    const float* W_W2     = (const float*)d_in[7];
    const float* W_U2     = (const float*)d_in[8];
    const float* W_a2     = (const float*)d_in[9];
    const int*   edge_src = (const int*)  d_in[10];

    static __half *zp = nullptr, *zip = nullptr, *hp = nullptr;
    static float  *ssp = nullptr, *sdp = nullptr;
    static int smem_bytes = 0;
    if (!zp) {
        cudaGetSymbolAddress((void**)&zp,  g_z);
        cudaGetSymbolAddress((void**)&zip, g_zi);
        cudaGetSymbolAddress((void**)&hp,  g_h);
        cudaGetSymbolAddress((void**)&ssp, g_ss);
        cudaGetSymbolAddress((void**)&sdp, g_sd);
        smem_bytes = 6 * 128 * LDA * (int)sizeof(__nv_bfloat16) + 256 * (int)sizeof(float);
        cudaFuncSetAttribute(gat_gemm_kernel<float>,
                             cudaFuncAttributeMaxDynamicSharedMemorySize, smem_bytes);
        cudaFuncSetAttribute(gat_gemm_kernel<__half>,
                             cudaFuncAttributeMaxDynamicSharedMemorySize, smem_bytes);
    }

    const int gemm_blocks = 152;                      // persistent, 1 CTA/SM
    const int attn_blocks = (NNODES + 7) / 8;         // 12500

    // Layer 1
    gat_gemm_kernel<float><<<gemm_blocks, 512, smem_bytes>>>(
        attr, W_W1, W_U1, W_a1, zp, zip, ssp, sdp);
    gat_attn_kernel<true><<<attn_blocks, 256>>>(
        edge_src, edge_d, W_V1, W_a1, zp, zip, ssp, sdp, hp);
    // Layer 2
    gat_gemm_kernel<__half><<<gemm_blocks, 512, smem_bytes>>>(
        hp, W_W2, W_U2, W_a2, zp, zip, ssp, sdp);
    gat_attn_kernel<false><<<attn_blocks, 256>>>(
        edge_src, edge_d, W_V2, W_a2, zp, zip, ssp, sdp, d_out);
}

// round 15
// speedup vs baseline: 1.5673x; 1.0969x over previous
#include <cuda_runtime.h>
#include <cuda_fp16.h>
#include <cstdint>

#define NNODES 100000
#define DEG     16
#define DIM     128
#define NTILES  ((NNODES + 127) / 128)     // 782
#define NEG_SLOPE 0.01f
#define LDA 136   // fp16 elems per smem row (128 + 8 pad) -> conflict-free ldmatrix

// ---------------- scratch (static device globals; no allocation) ----------------
__device__ __half g_z [NNODES * DIM];
__device__ __half g_zi[NNODES * DIM];
__device__ __half g_h [NNODES * DIM];
__device__ float  g_ss[NNODES];
__device__ float  g_sd[NNODES];

// ---------------- PTX helpers ----------------
static __device__ __forceinline__ uint32_t sptr(const void* p) {
    return (uint32_t)__cvta_generic_to_shared(p);
}
static __device__ __forceinline__ void ldsm4(uint32_t* r, uint32_t addr) {
    asm volatile("ldmatrix.sync.aligned.m8n8.x4.shared.b16 {%0,%1,%2,%3}, [%4];"
                 : "=r"(r[0]), "=r"(r[1]), "=r"(r[2]), "=r"(r[3]) : "r"(addr));
}
static __device__ __forceinline__ void ldsm4t(uint32_t* r, uint32_t addr) {
    asm volatile("ldmatrix.sync.aligned.m8n8.x4.trans.shared.b16 {%0,%1,%2,%3}, [%4];"
                 : "=r"(r[0]), "=r"(r[1]), "=r"(r[2]), "=r"(r[3]) : "r"(addr));
}
static __device__ __forceinline__ void mma16816(float* c, const uint32_t* a,
                                                uint32_t b0, uint32_t b1) {
    asm volatile(
        "mma.sync.aligned.m16n8k16.row.col.f32.f16.f16.f32 "
        "{%0,%1,%2,%3}, {%4,%5,%6,%7}, {%8,%9}, {%0,%1,%2,%3};"
        : "+f"(c[0]), "+f"(c[1]), "+f"(c[2]), "+f"(c[3])
        : "r"(a[0]), "r"(a[1]), "r"(a[2]), "r"(a[3]), "r"(b0), "r"(b1));
}
static __device__ __forceinline__ void split_h16(float v, __half& hi, __half& lo) {
    hi = __float2half_rn(v);
    lo = __float2half_rn(v - __half2float(hi));
}

// fill sB[k][n] (hi/lo fp16) from row-major W[n][k]; 512 threads
static __device__ __forceinline__ void fill_w(const float* __restrict__ W,
                                              __half* sBhi, __half* sBlo, int tid) {
#pragma unroll
    for (int p = 0; p < 8; p++) {
        int idx = tid + p * 512;          // 0..4095 (float4 units)
        int k4  = idx >> 7;               // 0..31
        int n   = idx & 127;
        float4 v = *(const float4*)&W[n * DIM + k4 * 4];
        float vv[4] = {v.x, v.y, v.z, v.w};
#pragma unroll
        for (int i = 0; i < 4; i++) {
            __half hi, lo;
            split_h16(vv[i], hi, lo);
            int k = k4 * 4 + i;
            sBhi[k * LDA + n] = hi;
            sBlo[k * LDA + n] = lo;
        }
    }
}

// load 4 consecutive input values as float4 (fp32 or fp16 source)
template <typename Tin>
static __device__ __forceinline__ float4 load4(const Tin* p) {
    if constexpr (sizeof(Tin) == 4) {
        return *(const float4*)p;
    } else {
        float2 raw = *(const float2*)p;                  // 4 halves
        float2 f01 = __half22float2(*(__half2*)&raw.x);
        float2 f23 = __half22float2(*(__half2*)&raw.y);
        return make_float4(f01.x, f01.y, f23.x, f23.y);
    }
}

// ---------------------------------------------------------------------------
// Persistent GEMM: weights staged ONCE per CTA; grid-stride over 128-row tiles.
//   z  = h@Ww^T (+ fused s_src/s_dst),  zi = h@Wu^T
// fp16 hi/lo split, fp32 accum.
//   ATERMS=2 (fp32 input): C = AhiBhi + AhiBlo + AloBhi   (error ~2^-22)
//   ATERMS=1 (fp16 input): C = A(Bhi) + A(Blo)            (A exact)
// ---------------------------------------------------------------------------
template <typename Tin, int ATERMS>
__global__ __launch_bounds__(512) void gat_gemm_kernel(
    const Tin*   __restrict__ h,
    const float* __restrict__ Ww,
    const float* __restrict__ Wu,
    const float* __restrict__ Wa,
    __half* __restrict__ z,
    __half* __restrict__ zi,
    float*  __restrict__ ssrc,
    float*  __restrict__ sdst)
{
    extern __shared__ __align__(16) char smem_raw[];
    __half* sAhi  = (__half*)smem_raw;
    __half* sAlo  = sAhi  + 128 * LDA;
    __half* sBhi0 = sAlo  + 128 * LDA;
    __half* sBlo0 = sBhi0 + 128 * LDA;
    __half* sBhi1 = sBlo0 + 128 * LDA;
    __half* sBlo1 = sBhi1 + 128 * LDA;
    float*  sred  = (float*)(sBlo1 + 128 * LDA);  // [256]: 0..127 src, 128..255 dst

    const int tid  = threadIdx.x;
    const int lane = tid & 31;
    const int warp = tid >> 5;      // 0..15
    const int wm   = warp & 7;      // 16-row strip
    const int wn   = warp >> 3;     // 64-col strip

    // ---- stage both weight matrices ONCE ----
    fill_w(Ww, sBhi0, sBlo0, tid);
    fill_w(Wu, sBhi1, sBlo1, tid);

    const int arow  = lane & 15;
    const int acolh = (lane >> 4) * 8;

    for (int tile = blockIdx.x; tile < NTILES; tile += gridDim.x) {
        const int row0 = tile * 128;
        if (tid < 256) sred[tid] = 0.f;

        // ---- stage A tile (input -> fp16 hi[/lo]) ----
#pragma unroll
        for (int p = 0; p < 8; p++) {
            int idx = tid + p * 512;    // 0..4095 (4-elem units)
            int r   = idx >> 5;
            int c4  = idx & 31;
            float4 v = make_float4(0.f, 0.f, 0.f, 0.f);
            int row = row0 + r;
            if (row < NNODES) v = load4(&h[row * DIM + c4 * 4]);
            float vv[4] = {v.x, v.y, v.z, v.w};
            __half hi[4], lo[4];
#pragma unroll
            for (int i = 0; i < 4; i++) split_h16(vv[i], hi[i], lo[i]);
            __half2* ph = (__half2*)&sAhi[r * LDA + c4 * 4];
            ph[0] = __halves2half2(hi[0], hi[1]);
            ph[1] = __halves2half2(hi[2], hi[3]);
            if constexpr (ATERMS == 2) {
                __half2* pl = (__half2*)&sAlo[r * LDA + c4 * 4];
                pl[0] = __halves2half2(lo[0], lo[1]);
                pl[1] = __halves2half2(lo[2], lo[3]);
            }
        }
        __syncthreads();   // A ready, sred zeroed, (first iter: B ready)

        // ---- fused mainloop: both accumulator sets share A fragments ----
        float cz[8][4], cu[8][4];
#pragma unroll
        for (int t = 0; t < 8; t++)
#pragma unroll
            for (int i = 0; i < 4; i++) { cz[t][i] = 0.f; cu[t][i] = 0.f; }

#pragma unroll 1
        for (int kb = 0; kb < DIM; kb += 16) {
            uint32_t ahi[4], alo[4];
            {
                int off = (wm * 16 + arow) * LDA + kb + acolh;
                ldsm4(ahi, sptr(&sAhi[off]));
                if constexpr (ATERMS == 2) ldsm4(alo, sptr(&sAlo[off]));
            }
#pragma unroll
            for (int q = 0; q < 4; q++) {
                int boff = (kb + arow) * LDA + wn * 64 + q * 16 + acolh;
                uint32_t bh0[4], bl0[4], bh1[4], bl1[4];
                ldsm4t(bh0, sptr(&sBhi0[boff]));
                ldsm4t(bl0, sptr(&sBlo0[boff]));
                ldsm4t(bh1, sptr(&sBhi1[boff]));
                ldsm4t(bl1, sptr(&sBlo1[boff]));
#pragma unroll
                for (int half = 0; half < 2; half++) {
                    int t = q * 2 + half, hh = half * 2;
                    mma16816(cz[t], ahi, bh0[hh], bh0[hh + 1]);
                    mma16816(cu[t], ahi, bh1[hh], bh1[hh + 1]);
                    mma16816(cz[t], ahi, bl0[hh], bl0[hh + 1]);
                    mma16816(cu[t], ahi, bl1[hh], bl1[hh + 1]);
                    if constexpr (ATERMS == 2) {
                        mma16816(cz[t], alo, bh0[hh], bh0[hh + 1]);
                        mma16816(cu[t], alo, bh1[hh], bh1[hh + 1]);
                    }
                }
            }
        }

        // ---- epilogue: write z, zi (fp16), fused s_src/s_dst ----
        float ps[2] = {0.f, 0.f}, pd[2] = {0.f, 0.f};
#pragma unroll
        for (int t = 0; t < 8; t++) {
            int col = wn * 64 + t * 8 + (lane & 3) * 2;
            float as0 = Wa[col],       as1 = Wa[col + 1];
            float ad0 = Wa[DIM + col], ad1 = Wa[DIM + col + 1];
#pragma unroll
            for (int hh = 0; hh < 2; hh++) {
                int row = row0 + wm * 16 + hh * 8 + (lane >> 2);
                if (row < NNODES) {
                    *(__half2*)&z [row * DIM + col] =
                        __floats2half2_rn(cz[t][hh * 2], cz[t][hh * 2 + 1]);
                    *(__half2*)&zi[row * DIM + col] =
                        __floats2half2_rn(cu[t][hh * 2], cu[t][hh * 2 + 1]);
                }
                ps[hh] = fmaf(cz[t][hh * 2], as0, fmaf(cz[t][hh * 2 + 1], as1, ps[hh]));
                pd[hh] = fmaf(cz[t][hh * 2], ad0, fmaf(cz[t][hh * 2 + 1], ad1, pd[hh]));
            }
        }
#pragma unroll
        for (int hh = 0; hh < 2; hh++) {
#pragma unroll
            for (int off = 1; off <= 2; off <<= 1) {
                ps[hh] += __shfl_xor_sync(0xffffffffu, ps[hh], off);
                pd[hh] += __shfl_xor_sync(0xffffffffu, pd[hh], off);
            }
        }
        if ((lane & 3) == 0) {
#pragma unroll
            for (int hh = 0; hh < 2; hh++) {
                int lr = wm * 16 + hh * 8 + (lane >> 2);
                atomicAdd(&sred[lr],       ps[hh]);
                atomicAdd(&sred[128 + lr], pd[hh]);
            }
        }
        __syncthreads();
        if (tid < 256) {
            int which = tid >> 7;           // 0 = src, 1 = dst
            int r     = tid & 127;
            int row   = row0 + r;
            if (row < NNODES) {
                float s = sred[which * 128 + r];
                if (which) sdst[row] = s; else ssrc[row] = s;
            }
        }
        __syncthreads();   // protect sA / sred before next tile
    }
}

// ---------------------------------------------------------------------------
// Attention kernel: TWO nodes per warp (16 lanes each, lane owns 8 columns).
// Edges of node i are contiguous [i*16, i*16+16); DEG == 16 == half-warp.
// ---------------------------------------------------------------------------
template <bool OUT_HALF>
__global__ __launch_bounds__(256) void gat_attn_kernel(
    const int*    __restrict__ edge_src,
    const float*  __restrict__ edge_d,
    const float*  __restrict__ Wv,
    const float*  __restrict__ Wa,
    const __half* __restrict__ z,
    const __half* __restrict__ zi,
    const float*  __restrict__ ssrc,
    const float*  __restrict__ sdst,
    void* __restrict__ outv)
{
    const int gw   = (blockIdx.x * blockDim.x + threadIdx.x) >> 5;
    const int lane = threadIdx.x & 31;
    const int hl   = lane & 15;
    const int node = gw * 2 + (lane >> 4);
    if (node >= NNODES) return;

    const float cE = Wv[0] * Wa[2 * DIM];
    const float sd = sdst[node];

    const int src = edge_src[node * DEG + hl];
    float ev = ssrc[src] + sd + cE * edge_d[node * DEG + hl];
    float e  = (ev > 0.f) ? ev : NEG_SLOPE * ev;

    // 16-lane softmax (xor offsets <= 8 stay within each half-warp)
    float m = e;
#pragma unroll
    for (int off = 8; off >= 1; off >>= 1)
        m = fmaxf(m, __shfl_xor_sync(0xffffffffu, m, off));
    float ex = expf(e - m);
    float s  = ex;
#pragma unroll
    for (int off = 8; off >= 1; off >>= 1)
        s += __shfl_xor_sync(0xffffffffu, s, off);
    const float alpha = ex / s;

    // weighted gather: lane owns 8 columns (16B of fp16)
    const int col  = hl * 8;
    const int base = lane & 16;
    float acc[8];
#pragma unroll
    for (int i = 0; i < 8; i++) acc[i] = 0.f;

#pragma unroll
    for (int j = 0; j < DEG; j++) {
        int   idx = base + j;
        int   sj  = __shfl_sync(0xffffffffu, src,   idx);
        float aj  = __shfl_sync(0xffffffffu, alpha, idx);
        float4 raw = *(const float4*)&z[sj * DIM + col];   // 8 halves
        const __half2* hp = (const __half2*)&raw;
#pragma unroll
        for (int q = 0; q < 4; q++) {
            float2 f = __half22float2(hp[q]);
            acc[q * 2]     = fmaf(aj, f.x, acc[q * 2]);
            acc[q * 2 + 1] = fmaf(aj, f.y, acc[q * 2 + 1]);
        }
    }

    float4 rawzi = *(const float4*)&zi[node * DIM + col];
    const __half2* zp2 = (const __half2*)&rawzi;
    float o[8];
#pragma unroll
    for (int q = 0; q < 4; q++) {
        float2 f = __half22float2(zp2[q]);
        o[q * 2]     = fmaxf(f.x + acc[q * 2],     0.f);
        o[q * 2 + 1] = fmaxf(f.y + acc[q * 2 + 1], 0.f);
    }

    if constexpr (OUT_HALF) {
        float4 packed;
        __half2* ph = (__half2*)&packed;
#pragma unroll
        for (int q = 0; q < 4; q++) ph[q] = __floats2half2_rn(o[q * 2], o[q * 2 + 1]);
        *(float4*)&((__half*)outv)[node * DIM + col] = packed;
    } else {
        float* out = (float*)outv;
        *(float4*)&out[node * DIM + col]     = make_float4(o[0], o[1], o[2], o[3]);
        *(float4*)&out[node * DIM + col + 4] = make_float4(o[4], o[5], o[6], o[7]);
    }
}

// ---------------------------------------------------------------------------
extern "C" void kernel_launch(void* const* d_in, const int* in_sizes, int n_in,
                              void* d_out, int out_size) {
    const float* attr     = (const float*)d_in[0];
    const float* edge_d   = (const float*)d_in[1];
    const float* W_V1     = (const float*)d_in[2];
    const float* W_W1     = (const float*)d_in[3];
    const float* W_U1     = (const float*)d_in[4];
    const float* W_a1     = (const float*)d_in[5];
    const float* W_V2     = (const float*)d_in[6];
    const float* W_W2     = (const float*)d_in[7];
    const float* W_U2     = (const float*)d_in[8];
    const float* W_a2     = (const float*)d_in[9];
    const int*   edge_src = (const int*)  d_in[10];

    static __half *zp = nullptr, *zip = nullptr, *hp = nullptr;
    static float  *ssp = nullptr, *sdp = nullptr;
    static int smem_bytes = 0;
    if (!zp) {
        cudaGetSymbolAddress((void**)&zp,  g_z);
        cudaGetSymbolAddress((void**)&zip, g_zi);
        cudaGetSymbolAddress((void**)&hp,  g_h);
        cudaGetSymbolAddress((void**)&ssp, g_ss);
        cudaGetSymbolAddress((void**)&sdp, g_sd);
        smem_bytes = 6 * 128 * LDA * (int)sizeof(__half) + 256 * (int)sizeof(float);
        cudaFuncSetAttribute(gat_gemm_kernel<float, 2>,
                             cudaFuncAttributeMaxDynamicSharedMemorySize, smem_bytes);
        cudaFuncSetAttribute(gat_gemm_kernel<__half, 1>,
                             cudaFuncAttributeMaxDynamicSharedMemorySize, smem_bytes);
    }

    const int gemm_blocks = 152;                          // persistent, 1 CTA/SM
    const int attn_blocks = (NNODES / 2 + 7) / 8;         // 6250 (2 nodes/warp, 8 warps/blk)

    // Layer 1
    gat_gemm_kernel<float, 2><<<gemm_blocks, 512, smem_bytes>>>(
        attr, W_W1, W_U1, W_a1, zp, zip, ssp, sdp);
    gat_attn_kernel<true><<<attn_blocks, 256>>>(
        edge_src, edge_d, W_V1, W_a1, zp, zip, ssp, sdp, hp);
    // Layer 2
    gat_gemm_kernel<__half, 1><<<gemm_blocks, 512, smem_bytes>>>(
        hp, W_W2, W_U2, W_a2, zp, zip, ssp, sdp);
    gat_attn_kernel<false><<<attn_blocks, 256>>>(
        edge_src, edge_d, W_V2, W_a2, zp, zip, ssp, sdp, d_out);
}

// round 17
// speedup vs baseline: 1.6960x; 1.0821x over previous
#include <cuda_runtime.h>
#include <cuda_fp16.h>
#include <cstdint>

#define NNODES 100000
#define DEG     16
#define DIM     128
#define NTILES  ((NNODES + 127) / 128)     // 782
#define NEG_SLOPE 0.01f
#define LDA 136   // fp16 elems per smem row (128 + 8 pad) -> conflict-free ldmatrix

// ---------------- scratch (static device globals; no allocation) ----------------
__device__ __half g_z [NNODES * DIM];
__device__ __half g_zi[NNODES * DIM];
__device__ __half g_h [NNODES * DIM];
__device__ float  g_ss[NNODES];
__device__ float  g_sd[NNODES];

// ---------------- PTX helpers ----------------
static __device__ __forceinline__ uint32_t sptr(const void* p) {
    return (uint32_t)__cvta_generic_to_shared(p);
}
static __device__ __forceinline__ void ldsm4(uint32_t* r, uint32_t addr) {
    asm volatile("ldmatrix.sync.aligned.m8n8.x4.shared.b16 {%0,%1,%2,%3}, [%4];"
                 : "=r"(r[0]), "=r"(r[1]), "=r"(r[2]), "=r"(r[3]) : "r"(addr));
}
static __device__ __forceinline__ void ldsm4t(uint32_t* r, uint32_t addr) {
    asm volatile("ldmatrix.sync.aligned.m8n8.x4.trans.shared.b16 {%0,%1,%2,%3}, [%4];"
                 : "=r"(r[0]), "=r"(r[1]), "=r"(r[2]), "=r"(r[3]) : "r"(addr));
}
static __device__ __forceinline__ void mma16816(float* c, const uint32_t* a,
                                                uint32_t b0, uint32_t b1) {
    asm volatile(
        "mma.sync.aligned.m16n8k16.row.col.f32.f16.f16.f32 "
        "{%0,%1,%2,%3}, {%4,%5,%6,%7}, {%8,%9}, {%0,%1,%2,%3};"
        : "+f"(c[0]), "+f"(c[1]), "+f"(c[2]), "+f"(c[3])
        : "r"(a[0]), "r"(a[1]), "r"(a[2]), "r"(a[3]), "r"(b0), "r"(b1));
}
static __device__ __forceinline__ void split_h16(float v, __half& hi, __half& lo) {
    hi = __float2half_rn(v);
    lo = __float2half_rn(v - __half2float(hi));
}

// fill sB[k][n] (hi/lo fp16) from row-major W[n][k]; 512 threads
static __device__ __forceinline__ void fill_w(const float* __restrict__ W,
                                              __half* sBhi, __half* sBlo, int tid) {
#pragma unroll
    for (int p = 0; p < 8; p++) {
        int idx = tid + p * 512;          // 0..4095 (float4 units)
        int k4  = idx >> 7;               // 0..31
        int n   = idx & 127;
        float4 v = *(const float4*)&W[n * DIM + k4 * 4];
        float vv[4] = {v.x, v.y, v.z, v.w};
#pragma unroll
        for (int i = 0; i < 4; i++) {
            __half hi, lo;
            split_h16(vv[i], hi, lo);
            int k = k4 * 4 + i;
            sBhi[k * LDA + n] = hi;
            sBlo[k * LDA + n] = lo;
        }
    }
}

// load 4 consecutive input values as float4 (fp32 or fp16 source)
template <typename Tin>
static __device__ __forceinline__ float4 load4(const Tin* p) {
    if constexpr (sizeof(Tin) == 4) {
        return *(const float4*)p;
    } else {
        float2 raw = *(const float2*)p;                  // 4 halves
        float2 f01 = __half22float2(*(__half2*)&raw.x);
        float2 f23 = __half22float2(*(__half2*)&raw.y);
        return make_float4(f01.x, f01.y, f23.x, f23.y);
    }
}

// ---------------------------------------------------------------------------
// Persistent GEMM: weights staged ONCE per CTA; grid-stride over 128-row tiles.
//   z  = h@Ww^T (+ fused s_src/s_dst),  zi = h@Wu^T
// A rounded to fp16 (exact when input already fp16); B split hi/lo fp16:
//   C = A*Bhi + A*Blo    (B error ~2^-22; A rounding ~2^-11 on fp32 inputs)
// ---------------------------------------------------------------------------
template <typename Tin>
__global__ __launch_bounds__(512) void gat_gemm_kernel(
    const Tin*   __restrict__ h,
    const float* __restrict__ Ww,
    const float* __restrict__ Wu,
    const float* __restrict__ Wa,
    __half* __restrict__ z,
    __half* __restrict__ zi,
    float*  __restrict__ ssrc,
    float*  __restrict__ sdst)
{
    extern __shared__ __align__(16) char smem_raw[];
    __half* sA    = (__half*)smem_raw;
    __half* sBhi0 = sA    + 128 * LDA;
    __half* sBlo0 = sBhi0 + 128 * LDA;
    __half* sBhi1 = sBlo0 + 128 * LDA;
    __half* sBlo1 = sBhi1 + 128 * LDA;
    float*  sred  = (float*)(sBlo1 + 128 * LDA);  // [256]: 0..127 src, 128..255 dst

    const int tid  = threadIdx.x;
    const int lane = tid & 31;
    const int warp = tid >> 5;      // 0..15
    const int wm   = warp & 7;      // 16-row strip
    const int wn   = warp >> 3;     // 64-col strip

    // ---- stage both weight matrices ONCE ----
    fill_w(Ww, sBhi0, sBlo0, tid);
    fill_w(Wu, sBhi1, sBlo1, tid);

    const int arow  = lane & 15;
    const int acolh = (lane >> 4) * 8;

    for (int tile = blockIdx.x; tile < NTILES; tile += gridDim.x) {
        const int row0 = tile * 128;
        if (tid < 256) sred[tid] = 0.f;

        // ---- stage A tile (input -> fp16) ----
#pragma unroll
        for (int p = 0; p < 8; p++) {
            int idx = tid + p * 512;    // 0..4095 (4-elem units)
            int r   = idx >> 5;
            int c4  = idx & 31;
            float4 v = make_float4(0.f, 0.f, 0.f, 0.f);
            int row = row0 + r;
            if (row < NNODES) v = load4(&h[row * DIM + c4 * 4]);
            __half2* ph = (__half2*)&sA[r * LDA + c4 * 4];
            ph[0] = __floats2half2_rn(v.x, v.y);
            ph[1] = __floats2half2_rn(v.z, v.w);
        }
        __syncthreads();   // A ready, sred zeroed, (first iter: B ready)

        // ---- fused mainloop: both accumulator sets share A fragments ----
        float cz[8][4], cu[8][4];
#pragma unroll
        for (int t = 0; t < 8; t++)
#pragma unroll
            for (int i = 0; i < 4; i++) { cz[t][i] = 0.f; cu[t][i] = 0.f; }

#pragma unroll 1
        for (int kb = 0; kb < DIM; kb += 16) {
            uint32_t a[4];
            {
                int off = (wm * 16 + arow) * LDA + kb + acolh;
                ldsm4(a, sptr(&sA[off]));
            }
#pragma unroll
            for (int q = 0; q < 4; q++) {
                int boff = (kb + arow) * LDA + wn * 64 + q * 16 + acolh;
                uint32_t bh0[4], bl0[4], bh1[4], bl1[4];
                ldsm4t(bh0, sptr(&sBhi0[boff]));
                ldsm4t(bl0, sptr(&sBlo0[boff]));
                ldsm4t(bh1, sptr(&sBhi1[boff]));
                ldsm4t(bl1, sptr(&sBlo1[boff]));
#pragma unroll
                for (int half = 0; half < 2; half++) {
                    int t = q * 2 + half, hh = half * 2;
                    mma16816(cz[t], a, bh0[hh], bh0[hh + 1]);
                    mma16816(cu[t], a, bh1[hh], bh1[hh + 1]);
                    mma16816(cz[t], a, bl0[hh], bl0[hh + 1]);
                    mma16816(cu[t], a, bl1[hh], bl1[hh + 1]);
                }
            }
        }

        // ---- epilogue: write z, zi (fp16), fused s_src/s_dst ----
        float ps[2] = {0.f, 0.f}, pd[2] = {0.f, 0.f};
#pragma unroll
        for (int t = 0; t < 8; t++) {
            int col = wn * 64 + t * 8 + (lane & 3) * 2;
            float as0 = Wa[col],       as1 = Wa[col + 1];
            float ad0 = Wa[DIM + col], ad1 = Wa[DIM + col + 1];
#pragma unroll
            for (int hh = 0; hh < 2; hh++) {
                int row = row0 + wm * 16 + hh * 8 + (lane >> 2);
                if (row < NNODES) {
                    *(__half2*)&z [row * DIM + col] =
                        __floats2half2_rn(cz[t][hh * 2], cz[t][hh * 2 + 1]);
                    *(__half2*)&zi[row * DIM + col] =
                        __floats2half2_rn(cu[t][hh * 2], cu[t][hh * 2 + 1]);
                }
                ps[hh] = fmaf(cz[t][hh * 2], as0, fmaf(cz[t][hh * 2 + 1], as1, ps[hh]));
                pd[hh] = fmaf(cz[t][hh * 2], ad0, fmaf(cz[t][hh * 2 + 1], ad1, pd[hh]));
            }
        }
#pragma unroll
        for (int hh = 0; hh < 2; hh++) {
#pragma unroll
            for (int off = 1; off <= 2; off <<= 1) {
                ps[hh] += __shfl_xor_sync(0xffffffffu, ps[hh], off);
                pd[hh] += __shfl_xor_sync(0xffffffffu, pd[hh], off);
            }
        }
        if ((lane & 3) == 0) {
#pragma unroll
            for (int hh = 0; hh < 2; hh++) {
                int lr = wm * 16 + hh * 8 + (lane >> 2);
                atomicAdd(&sred[lr],       ps[hh]);
                atomicAdd(&sred[128 + lr], pd[hh]);
            }
        }
        __syncthreads();
        if (tid < 256) {
            int which = tid >> 7;           // 0 = src, 1 = dst
            int r     = tid & 127;
            int row   = row0 + r;
            if (row < NNODES) {
                float s = sred[which * 128 + r];
                if (which) sdst[row] = s; else ssrc[row] = s;
            }
        }
        __syncthreads();   // protect sA / sred before next tile
    }
}

// ---------------------------------------------------------------------------
// Attention kernel: TWO nodes per warp (16 lanes each, lane owns 8 columns).
// Gather batched 2x8 float4 loads in flight (64-reg budget via launch_bounds).
// ---------------------------------------------------------------------------
template <bool OUT_HALF>
__global__ __launch_bounds__(256, 4) void gat_attn_kernel(
    const int*    __restrict__ edge_src,
    const float*  __restrict__ edge_d,
    const float*  __restrict__ Wv,
    const float*  __restrict__ Wa,
    const __half* __restrict__ z,
    const __half* __restrict__ zi,
    const float*  __restrict__ ssrc,
    const float*  __restrict__ sdst,
    void* __restrict__ outv)
{
    const int gw   = (blockIdx.x * blockDim.x + threadIdx.x) >> 5;
    const int lane = threadIdx.x & 31;
    const int hl   = lane & 15;
    const int node = gw * 2 + (lane >> 4);
    if (node >= NNODES) return;

    const float cE = Wv[0] * Wa[2 * DIM];
    const float sd = sdst[node];

    const int src = edge_src[node * DEG + hl];
    float ev = ssrc[src] + sd + cE * edge_d[node * DEG + hl];
    float e  = (ev > 0.f) ? ev : NEG_SLOPE * ev;

    // 16-lane softmax (xor offsets <= 8 stay within each half-warp)
    float m = e;
#pragma unroll
    for (int off = 8; off >= 1; off >>= 1)
        m = fmaxf(m, __shfl_xor_sync(0xffffffffu, m, off));
    float ex = expf(e - m);
    float s  = ex;
#pragma unroll
    for (int off = 8; off >= 1; off >>= 1)
        s += __shfl_xor_sync(0xffffffffu, s, off);
    const float alpha = ex / s;

    // weighted gather: lane owns 8 columns; loads batched 8-deep for MLP
    const int col  = hl * 8;
    const int base = lane & 16;
    float acc[8];
#pragma unroll
    for (int i = 0; i < 8; i++) acc[i] = 0.f;

#pragma unroll
    for (int b = 0; b < 2; b++) {
        float4 raw[8];
        float  aj[8];
#pragma unroll
        for (int j = 0; j < 8; j++) {
            int idx = base + b * 8 + j;
            int sj  = __shfl_sync(0xffffffffu, src,   idx);
            aj[j]   = __shfl_sync(0xffffffffu, alpha, idx);
            raw[j]  = *(const float4*)&z[sj * DIM + col];   // 8 halves
        }
#pragma unroll
        for (int j = 0; j < 8; j++) {
            const __half2* hp = (const __half2*)&raw[j];
#pragma unroll
            for (int q = 0; q < 4; q++) {
                float2 f = __half22float2(hp[q]);
                acc[q * 2]     = fmaf(aj[j], f.x, acc[q * 2]);
                acc[q * 2 + 1] = fmaf(aj[j], f.y, acc[q * 2 + 1]);
            }
        }
    }

    float4 rawzi = *(const float4*)&zi[node * DIM + col];
    const __half2* zp2 = (const __half2*)&rawzi;
    float o[8];
#pragma unroll
    for (int q = 0; q < 4; q++) {
        float2 f = __half22float2(zp2[q]);
        o[q * 2]     = fmaxf(f.x + acc[q * 2],     0.f);
        o[q * 2 + 1] = fmaxf(f.y + acc[q * 2 + 1], 0.f);
    }

    if constexpr (OUT_HALF) {
        float4 packed;
        __half2* ph = (__half2*)&packed;
#pragma unroll
        for (int q = 0; q < 4; q++) ph[q] = __floats2half2_rn(o[q * 2], o[q * 2 + 1]);
        *(float4*)&((__half*)outv)[node * DIM + col] = packed;
    } else {
        float* out = (float*)outv;
        *(float4*)&out[node * DIM + col]     = make_float4(o[0], o[1], o[2], o[3]);
        *(float4*)&out[node * DIM + col + 4] = make_float4(o[4], o[5], o[6], o[7]);
    }
}

// ---------------------------------------------------------------------------
extern "C" void kernel_launch(void* const* d_in, const int* in_sizes, int n_in,
                              void* d_out, int out_size) {
    const float* attr     = (const float*)d_in[0];
    const float* edge_d   = (const float*)d_in[1];
    const float* W_V1     = (const float*)d_in[2];
    const float* W_W1     = (const float*)d_in[3];
    const float* W_U1     = (const float*)d_in[4];
    const float* W_a1     = (const float*)d_in[5];
    const float* W_V2     = (const float*)d_in[6];
    const float* W_W2     = (const float*)d_in[7];
    const float* W_U2     = (const float*)d_in[8];
    const float* W_a2     = (const float*)d_in[9];
    const int*   edge_src = (const int*)  d_in[10];

    static __half *zp = nullptr, *zip = nullptr, *hp = nullptr;
    static float  *ssp = nullptr, *sdp = nullptr;
    static int smem_bytes = 0;
    if (!zp) {
        cudaGetSymbolAddress((void**)&zp,  g_z);
        cudaGetSymbolAddress((void**)&zip, g_zi);
        cudaGetSymbolAddress((void**)&hp,  g_h);
        cudaGetSymbolAddress((void**)&ssp, g_ss);
        cudaGetSymbolAddress((void**)&sdp, g_sd);
        smem_bytes = 5 * 128 * LDA * (int)sizeof(__half) + 256 * (int)sizeof(float);
        cudaFuncSetAttribute(gat_gemm_kernel<float>,
                             cudaFuncAttributeMaxDynamicSharedMemorySize, smem_bytes);
        cudaFuncSetAttribute(gat_gemm_kernel<__half>,
                             cudaFuncAttributeMaxDynamicSharedMemorySize, smem_bytes);
    }

    const int gemm_blocks = 152;                          // persistent, 1 CTA/SM
    const int attn_blocks = (NNODES / 2 + 7) / 8;         // 6250 (2 nodes/warp)

    // Layer 1
    gat_gemm_kernel<float><<<gemm_blocks, 512, smem_bytes>>>(
        attr, W_W1, W_U1, W_a1, zp, zip, ssp, sdp);
    gat_attn_kernel<true><<<attn_blocks, 256>>>(
        edge_src, edge_d, W_V1, W_a1, zp, zip, ssp, sdp, hp);
    // Layer 2
    gat_gemm_kernel<__half><<<gemm_blocks, 512, smem_bytes>>>(
        hp, W_W2, W_U2, W_a2, zp, zip, ssp, sdp);
    gat_attn_kernel<false><<<attn_blocks, 256>>>(
        edge_src, edge_d, W_V2, W_a2, zp, zip, ssp, sdp, d_out);
}